// round 8
// baseline (speedup 1.0000x reference)
#include <cuda_runtime.h>
#include <cstdint>

#define D_MODEL 768
#define NHEADS  12
#define DK      64
#define BATCH   2
#define SEQ     2048
#define MTOT    (BATCH*SEQ)   // 4096

// Scratch (device globals: allocation-free, harness-safe)
__device__ float g_q [BATCH*NHEADS*SEQ*DK];   // [B,H,S,dk]
__device__ float g_k [BATCH*NHEADS*SEQ*DK];
__device__ float g_v [BATCH*NHEADS*SEQ*DK];
__device__ float g_ao[MTOT*D_MODEL];          // [B,S,D] attention output

__device__ __forceinline__ uint32_t f2tf32(float x) {
    uint32_t r;
    asm("cvt.rna.tf32.f32 %0, %1;" : "=r"(r) : "f"(x));
    return r;
}
__device__ __forceinline__ float fexp2(float x) {
    float y;
    asm("ex2.approx.ftz.f32 %0, %1;" : "=f"(y) : "f"(x));
    return y;
}
__device__ __forceinline__ void mma_tf32(float c[4],
        uint32_t a0, uint32_t a1, uint32_t a2, uint32_t a3,
        uint32_t b0, uint32_t b1) {
    asm volatile(
        "mma.sync.aligned.m16n8k8.row.col.f32.tf32.tf32.f32 "
        "{%0,%1,%2,%3}, {%4,%5,%6,%7}, {%8,%9}, {%0,%1,%2,%3};"
        : "+f"(c[0]), "+f"(c[1]), "+f"(c[2]), "+f"(c[3])
        : "r"(a0), "r"(a1), "r"(a2), "r"(a3), "r"(b0), "r"(b1));
}

// ---------------------------------------------------------------------------
// 3xTF32 tensor-core GEMM with bias (fp32-accurate) — R6 version (proven).
// Block: 128(M) x 64(N), BK=32. 8 warps in 4(m) x 2(n); warp tile 32x32.
// mode 0/1/2: scatter into g_q/g_k/g_v head-split. mode 3: row-major outp.
// A==nullptr -> read from g_ao.
// ---------------------------------------------------------------------------
#define GM 128
#define GN 64
#define GK 32
#define APAD 36
#define BPAD 72
#define GEMM_SMEM ((2*128*APAD + 2*GK*BPAD) * 4)   // 55296 B

__global__ __launch_bounds__(256, 2) void gemm_tc(
        const float* __restrict__ A, const float* __restrict__ W,
        const float* __restrict__ bias, float* __restrict__ outp, int mode) {
    extern __shared__ float sm[];
    float* Ah = sm;                  // [128][APAD]
    float* Al = Ah + 128 * APAD;
    float* Bh = Al + 128 * APAD;     // [GK][BPAD]
    float* Bl = Bh + GK * BPAD;

    const float* __restrict__ Ain = A ? A : (const float*)g_ao;
    const int m0 = blockIdx.x * GM, n0 = blockIdx.y * GN;
    const int t = threadIdx.x, warp = t >> 5, lane = t & 31;
    const int g = lane >> 2, tig = lane & 3;
    const int wm = (warp & 3) * 32, wn = (warp >> 2) * 32;

    const int am = t >> 3, ak = (t & 7) * 4;
    const int bk = t >> 4, bn = (t & 15) * 4;

    float4 aS[4], bS[2];
    #pragma unroll
    for (int i = 0; i < 4; i++)
        aS[i] = *(const float4*)&Ain[(size_t)(m0 + am + i*32) * D_MODEL + ak];
    #pragma unroll
    for (int i = 0; i < 2; i++)
        bS[i] = *(const float4*)&W[(size_t)(bk + i*16) * D_MODEL + n0 + bn];

    float acc[2][4][4] = {};

    for (int kt = 0; kt < D_MODEL / GK; kt++) {
        #pragma unroll
        for (int i = 0; i < 4; i++) {
            float4 v = aS[i], h, l;
            h.x = __uint_as_float(f2tf32(v.x)); l.x = __uint_as_float(f2tf32(v.x - h.x));
            h.y = __uint_as_float(f2tf32(v.y)); l.y = __uint_as_float(f2tf32(v.y - h.y));
            h.z = __uint_as_float(f2tf32(v.z)); l.z = __uint_as_float(f2tf32(v.z - h.z));
            h.w = __uint_as_float(f2tf32(v.w)); l.w = __uint_as_float(f2tf32(v.w - h.w));
            *(float4*)&Ah[(am + i*32) * APAD + ak] = h;
            *(float4*)&Al[(am + i*32) * APAD + ak] = l;
        }
        #pragma unroll
        for (int i = 0; i < 2; i++) {
            float4 v = bS[i], h, l;
            h.x = __uint_as_float(f2tf32(v.x)); l.x = __uint_as_float(f2tf32(v.x - h.x));
            h.y = __uint_as_float(f2tf32(v.y)); l.y = __uint_as_float(f2tf32(v.y - h.y));
            h.z = __uint_as_float(f2tf32(v.z)); l.z = __uint_as_float(f2tf32(v.z - h.z));
            h.w = __uint_as_float(f2tf32(v.w)); l.w = __uint_as_float(f2tf32(v.w - h.w));
            *(float4*)&Bh[(bk + i*16) * BPAD + bn] = h;
            *(float4*)&Bl[(bk + i*16) * BPAD + bn] = l;
        }
        __syncthreads();

        if (kt + 1 < D_MODEL / GK) {
            const int k0 = (kt + 1) * GK;
            #pragma unroll
            for (int i = 0; i < 4; i++)
                aS[i] = *(const float4*)&Ain[(size_t)(m0 + am + i*32) * D_MODEL + k0 + ak];
            #pragma unroll
            for (int i = 0; i < 2; i++)
                bS[i] = *(const float4*)&W[(size_t)(k0 + bk + i*16) * D_MODEL + n0 + bn];
        }

        #pragma unroll
        for (int kk = 0; kk < 4; kk++) {
            uint32_t afh[2][4], afl[2][4];
            #pragma unroll
            for (int mi = 0; mi < 2; mi++) {
                const int r0 = (wm + mi*16 + g) * APAD + kk*8 + tig;
                const int r1 = r0 + 8 * APAD;
                afh[mi][0] = __float_as_uint(Ah[r0]);
                afh[mi][1] = __float_as_uint(Ah[r1]);
                afh[mi][2] = __float_as_uint(Ah[r0 + 4]);
                afh[mi][3] = __float_as_uint(Ah[r1 + 4]);
                afl[mi][0] = __float_as_uint(Al[r0]);
                afl[mi][1] = __float_as_uint(Al[r1]);
                afl[mi][2] = __float_as_uint(Al[r0 + 4]);
                afl[mi][3] = __float_as_uint(Al[r1 + 4]);
            }
            uint32_t bfh[4][2], bfl[4][2];
            #pragma unroll
            for (int nt = 0; nt < 4; nt++) {
                const int r = (kk*8 + tig) * BPAD + wn + nt*8 + g;
                bfh[nt][0] = __float_as_uint(Bh[r]);
                bfh[nt][1] = __float_as_uint(Bh[r + 4*BPAD]);
                bfl[nt][0] = __float_as_uint(Bl[r]);
                bfl[nt][1] = __float_as_uint(Bl[r + 4*BPAD]);
            }
            #pragma unroll
            for (int mi = 0; mi < 2; mi++)
                #pragma unroll
                for (int nt = 0; nt < 4; nt++) {
                    mma_tf32(acc[mi][nt], afh[mi][0], afh[mi][1], afh[mi][2], afh[mi][3],
                             bfh[nt][0], bfh[nt][1]);
                    mma_tf32(acc[mi][nt], afh[mi][0], afh[mi][1], afh[mi][2], afh[mi][3],
                             bfl[nt][0], bfl[nt][1]);
                    mma_tf32(acc[mi][nt], afl[mi][0], afl[mi][1], afl[mi][2], afl[mi][3],
                             bfh[nt][0], bfh[nt][1]);
                }
        }
        __syncthreads();
    }

    #pragma unroll
    for (int mi = 0; mi < 2; mi++) {
        #pragma unroll
        for (int nt = 0; nt < 4; nt++) {
            const int col = wn + nt*8 + 2*tig;
            const float b0 = bias[n0 + col];
            const float b1 = bias[n0 + col + 1];
            const int mA = m0 + wm + mi*16 + g;
            const int mB = mA + 8;
            float2 vA = { acc[mi][nt][0] + b0, acc[mi][nt][1] + b1 };
            float2 vB = { acc[mi][nt][2] + b0, acc[mi][nt][3] + b1 };
            if (mode == 3) {
                *(float2*)&outp[(size_t)mA * D_MODEL + n0 + col] = vA;
                *(float2*)&outp[(size_t)mB * D_MODEL + n0 + col] = vB;
            } else {
                float* o = (mode == 0) ? g_q : (mode == 1) ? g_k : g_v;
                const int h = n0 >> 6;
                const size_t iA = (((size_t)((mA >> 11) * NHEADS + h) * SEQ)
                                   + (mA & 2047)) * DK + col;
                const size_t iB = (((size_t)((mB >> 11) * NHEADS + h) * SEQ)
                                   + (mB & 2047)) * DK + col;
                *(float2*)&o[iA] = vA;
                *(float2*)&o[iB] = vB;
            }
        }
    }
}

// ---------------------------------------------------------------------------
// Tensor-core (tf32 HMMA) flash attention, double-buffered K/V tiles.
// Block: 128 queries of one (b,h); 8 warps x 16 query rows. 1 CTA/SM by design;
// latency hidden by prefetching next K/V tile into regs during compute.
// ---------------------------------------------------------------------------
#define KPAD 68
#define VPAD 72
#define PPAD 68
#define KBUF (64*KPAD)
#define VBUF (64*VPAD)
#define ATTN_SMEM_BYTES ((2*KBUF + 2*VBUF + 8*16*PPAD) * 4)  // 106496 B

__global__ __launch_bounds__(256) void flash_attn_tc() {
    extern __shared__ uint32_t smem_u[];
    uint32_t* Ks[2] = { smem_u, smem_u + KBUF };
    uint32_t* Vs[2] = { smem_u + 2*KBUF, smem_u + 2*KBUF + VBUF };
    float*    Psb   = (float*)(smem_u + 2*KBUF + 2*VBUF);   // 8 x [16][PPAD]

    const int t    = threadIdx.x;
    const int warp = t >> 5;
    const int lane = t & 31;
    const int g    = lane >> 2;
    const int tig  = lane & 3;

    const int qt = blockIdx.x, h = blockIdx.y, b = blockIdx.z;
    const size_t headBase = (size_t)(b * NHEADS + h) * SEQ * DK;
    const float* __restrict__ kp = g_k + headBase;
    const float* __restrict__ vp = g_v + headBase;

    // this thread's fixed K/V staging slots (4 float4 each per tile)
    const int ldr = t >> 2;            // row 0..63
    const int ldc = (t & 3) * 16;      // col 0,16,32,48

    const float qscale = 0.125f * 1.4426950408889634f;
    const int row_a = qt * 128 + warp * 16 + g;
    const float* __restrict__ qa = g_q + headBase + (size_t)row_a * DK;
    const float* __restrict__ qb = qa + 8 * DK;

    uint32_t qf[8][4];
    #pragma unroll
    for (int ks = 0; ks < 8; ks++) {
        const int c0 = 8 * ks + tig;
        qf[ks][0] = f2tf32(qa[c0]     * qscale);
        qf[ks][1] = f2tf32(qb[c0]     * qscale);
        qf[ks][2] = f2tf32(qa[c0 + 4] * qscale);
        qf[ks][3] = f2tf32(qb[c0 + 4] * qscale);
    }

    float o[8][4];
    #pragma unroll
    for (int nt = 0; nt < 8; nt++)
        #pragma unroll
        for (int c = 0; c < 4; c++) o[nt][c] = 0.f;
    float m0 = -1e30f, m1 = -1e30f, l0 = 0.f, l1 = 0.f;

    float* Pw = Psb + warp * 16 * PPAD;

    // ---- preload tile 0 ----
    float4 kS[4], vS[4];
    #pragma unroll
    for (int i = 0; i < 4; i++) {
        kS[i] = *(const float4*)&kp[(size_t)ldr * DK + ldc + i*4];
        vS[i] = *(const float4*)&vp[(size_t)ldr * DK + ldc + i*4];
    }
    #pragma unroll
    for (int i = 0; i < 4; i++) {
        uint4 ku = { f2tf32(kS[i].x), f2tf32(kS[i].y), f2tf32(kS[i].z), f2tf32(kS[i].w) };
        uint4 vu = { f2tf32(vS[i].x), f2tf32(vS[i].y), f2tf32(vS[i].z), f2tf32(vS[i].w) };
        *(uint4*)&Ks[0][ldr * KPAD + ldc + i*4] = ku;
        *(uint4*)&Vs[0][ldr * VPAD + ldc + i*4] = vu;
    }
    __syncthreads();

    const int NT = SEQ / 64;   // 32 k-tiles
    for (int kt = 0; kt < NT; kt++) {
        const int cur = kt & 1;
        const uint32_t* Ksu = Ks[cur];
        const uint32_t* Vsu = Vs[cur];

        // ---- issue next-tile LDGs now; consumed after compute ----
        if (kt + 1 < NT) {
            const size_t roff = (size_t)((kt + 1) * 64 + ldr) * DK + ldc;
            #pragma unroll
            for (int i = 0; i < 4; i++) {
                kS[i] = *(const float4*)&kp[roff + i*4];
                vS[i] = *(const float4*)&vp[roff + i*4];
            }
        }

        // ---- S = Q K^T ----
        float s[8][4];
        #pragma unroll
        for (int nt = 0; nt < 8; nt++) {
            #pragma unroll
            for (int c = 0; c < 4; c++) s[nt][c] = 0.f;
            const int key = nt * 8 + g;
            #pragma unroll
            for (int ks = 0; ks < 8; ks++) {
                const int d = ks * 8 + tig;
                uint32_t b0 = Ksu[key * KPAD + d];
                uint32_t b1 = Ksu[key * KPAD + d + 4];
                mma_tf32(s[nt], qf[ks][0], qf[ks][1], qf[ks][2], qf[ks][3], b0, b1);
            }
        }

        // ---- online softmax (base-2) ----
        float t0 = -1e30f, t1 = -1e30f;
        #pragma unroll
        for (int nt = 0; nt < 8; nt++) {
            t0 = fmaxf(t0, fmaxf(s[nt][0], s[nt][1]));
            t1 = fmaxf(t1, fmaxf(s[nt][2], s[nt][3]));
        }
        t0 = fmaxf(t0, __shfl_xor_sync(0xffffffffu, t0, 1));
        t0 = fmaxf(t0, __shfl_xor_sync(0xffffffffu, t0, 2));
        t1 = fmaxf(t1, __shfl_xor_sync(0xffffffffu, t1, 1));
        t1 = fmaxf(t1, __shfl_xor_sync(0xffffffffu, t1, 2));
        const float nm0 = fmaxf(m0, t0), nm1 = fmaxf(m1, t1);
        const float cr0 = fexp2(m0 - nm0), cr1 = fexp2(m1 - nm1);

        float p0 = 0.f, p1 = 0.f;
        #pragma unroll
        for (int nt = 0; nt < 8; nt++) {
            s[nt][0] = fexp2(s[nt][0] - nm0);
            s[nt][1] = fexp2(s[nt][1] - nm0);
            s[nt][2] = fexp2(s[nt][2] - nm1);
            s[nt][3] = fexp2(s[nt][3] - nm1);
            p0 += s[nt][0] + s[nt][1];
            p1 += s[nt][2] + s[nt][3];
        }
        p0 += __shfl_xor_sync(0xffffffffu, p0, 1);
        p0 += __shfl_xor_sync(0xffffffffu, p0, 2);
        p1 += __shfl_xor_sync(0xffffffffu, p1, 1);
        p1 += __shfl_xor_sync(0xffffffffu, p1, 2);
        l0 = l0 * cr0 + p0;
        l1 = l1 * cr1 + p1;
        m0 = nm0; m1 = nm1;

        #pragma unroll
        for (int nt = 0; nt < 8; nt++) {
            o[nt][0] *= cr0; o[nt][1] *= cr0;
            o[nt][2] *= cr1; o[nt][3] *= cr1;
        }

        // ---- P -> per-warp smem (tf32) ----
        #pragma unroll
        for (int nt = 0; nt < 8; nt++) {
            const int col = nt * 8 + 2 * tig;
            float2 lo = { __uint_as_float(f2tf32(s[nt][0])),
                          __uint_as_float(f2tf32(s[nt][1])) };
            float2 hi = { __uint_as_float(f2tf32(s[nt][2])),
                          __uint_as_float(f2tf32(s[nt][3])) };
            *(float2*)&Pw[g * PPAD + col]       = lo;
            *(float2*)&Pw[(g + 8) * PPAD + col] = hi;
        }
        __syncwarp();

        // ---- O += P V (A-frags per-ks: low reg pressure) ----
        #pragma unroll
        for (int ks = 0; ks < 8; ks++) {
            const int kk = ks * 8 + tig;
            const uint32_t a0 = __float_as_uint(Pw[g * PPAD + kk]);
            const uint32_t a1 = __float_as_uint(Pw[(g + 8) * PPAD + kk]);
            const uint32_t a2 = __float_as_uint(Pw[g * PPAD + kk + 4]);
            const uint32_t a3 = __float_as_uint(Pw[(g + 8) * PPAD + kk + 4]);
            const int key = ks * 8 + tig;
            #pragma unroll
            for (int nt = 0; nt < 8; nt++) {
                const int dcol = nt * 8 + g;
                uint32_t b0 = Vsu[key * VPAD + dcol];
                uint32_t b1 = Vsu[(key + 4) * VPAD + dcol];
                mma_tf32(o[nt], a0, a1, a2, a3, b0, b1);
            }
        }

        // ---- store prefetched tile into the other buffer, single sync ----
        if (kt + 1 < NT) {
            const int nxt = cur ^ 1;
            #pragma unroll
            for (int i = 0; i < 4; i++) {
                uint4 ku = { f2tf32(kS[i].x), f2tf32(kS[i].y),
                             f2tf32(kS[i].z), f2tf32(kS[i].w) };
                uint4 vu = { f2tf32(vS[i].x), f2tf32(vS[i].y),
                             f2tf32(vS[i].z), f2tf32(vS[i].w) };
                *(uint4*)&Ks[nxt][ldr * KPAD + ldc + i*4] = ku;
                *(uint4*)&Vs[nxt][ldr * VPAD + ldc + i*4] = vu;
            }
        }
        __syncthreads();
    }

    const float inv0 = 1.0f / l0, inv1 = 1.0f / l1;
    float* oa = g_ao + (size_t)(b * SEQ + row_a) * D_MODEL + h * DK;
    float* ob = oa + (size_t)8 * D_MODEL;
    #pragma unroll
    for (int nt = 0; nt < 8; nt++) {
        const int col = nt * 8 + 2 * tig;
        float2 lo = { o[nt][0] * inv0, o[nt][1] * inv0 };
        float2 hi = { o[nt][2] * inv1, o[nt][3] * inv1 };
        *(float2*)&oa[col] = lo;
        *(float2*)&ob[col] = hi;
    }
}

extern "C" void kernel_launch(void* const* d_in, const int* in_sizes, int n_in,
                              void* d_out, int out_size) {
    const float* q  = (const float*)d_in[0];
    const float* k  = (const float*)d_in[1];
    const float* v  = (const float*)d_in[2];
    const float* Wq = (const float*)d_in[3];
    const float* bq = (const float*)d_in[4];
    const float* Wk = (const float*)d_in[5];
    const float* bk = (const float*)d_in[6];
    const float* Wv = (const float*)d_in[7];
    const float* bv = (const float*)d_in[8];
    const float* Wo = (const float*)d_in[9];
    const float* bo = (const float*)d_in[10];
    float* out = (float*)d_out;

    cudaFuncSetAttribute(gemm_tc,
                         cudaFuncAttributeMaxDynamicSharedMemorySize, GEMM_SMEM);
    cudaFuncSetAttribute(flash_attn_tc,
                         cudaFuncAttributeMaxDynamicSharedMemorySize,
                         ATTN_SMEM_BYTES);

    dim3 gg(MTOT / GM, D_MODEL / GN);     // 32 x 12
    gemm_tc<<<gg, 256, GEMM_SMEM>>>(q, Wq, bq, nullptr, 0);
    gemm_tc<<<gg, 256, GEMM_SMEM>>>(k, Wk, bk, nullptr, 1);
    gemm_tc<<<gg, 256, GEMM_SMEM>>>(v, Wv, bv, nullptr, 2);

    dim3 ga(SEQ / 128, NHEADS, BATCH);    // 16 x 12 x 2
    flash_attn_tc<<<ga, 256, ATTN_SMEM_BYTES>>>();

    gemm_tc<<<gg, 256, GEMM_SMEM>>>(nullptr, Wo, bo, out, 3);
}

// round 13
// speedup vs baseline: 1.7286x; 1.7286x over previous
#include <cuda_runtime.h>
#include <cstdint>

#define D_MODEL 768
#define NHEADS  12
#define DK      64
#define BATCH   2
#define SEQ     2048
#define MTOT    (BATCH*SEQ)   // 4096

// Scratch (device globals: allocation-free, harness-safe)
__device__ float g_q [BATCH*NHEADS*SEQ*DK];   // [B,H,S,dk]
__device__ float g_k [BATCH*NHEADS*SEQ*DK];
__device__ float g_v [BATCH*NHEADS*SEQ*DK];
__device__ float g_ao[MTOT*D_MODEL];          // [B,S,D] attention output

__device__ __forceinline__ uint32_t f2tf32(float x) {
    uint32_t r;
    asm("cvt.rna.tf32.f32 %0, %1;" : "=r"(r) : "f"(x));
    return r;
}
__device__ __forceinline__ float fexp2(float x) {
    float y;
    asm("ex2.approx.ftz.f32 %0, %1;" : "=f"(y) : "f"(x));
    return y;
}
__device__ __forceinline__ void mma_tf32(float c[4],
        uint32_t a0, uint32_t a1, uint32_t a2, uint32_t a3,
        uint32_t b0, uint32_t b1) {
    asm volatile(
        "mma.sync.aligned.m16n8k8.row.col.f32.tf32.tf32.f32 "
        "{%0,%1,%2,%3}, {%4,%5,%6,%7}, {%8,%9}, {%0,%1,%2,%3};"
        : "+f"(c[0]), "+f"(c[1]), "+f"(c[2]), "+f"(c[3])
        : "r"(a0), "r"(a1), "r"(a2), "r"(a3), "r"(b0), "r"(b1));
}

// ---------------------------------------------------------------------------
// 3xTF32 tensor-core GEMM with bias (fp32-accurate) — R6 version (proven).
// Block: 128(M) x 64(N), BK=32. 8 warps in 4(m) x 2(n); warp tile 32x32.
// mode 0/1/2: scatter into g_q/g_k/g_v head-split. mode 3: row-major outp.
// A==nullptr -> read from g_ao.
// ---------------------------------------------------------------------------
#define GM 128
#define GN 64
#define GK 32
#define APAD 36
#define BPAD 72
#define GEMM_SMEM ((2*128*APAD + 2*GK*BPAD) * 4)   // 55296 B

__global__ __launch_bounds__(256, 2) void gemm_tc(
        const float* __restrict__ A, const float* __restrict__ W,
        const float* __restrict__ bias, float* __restrict__ outp, int mode) {
    extern __shared__ float sm[];
    float* Ah = sm;                  // [128][APAD]
    float* Al = Ah + 128 * APAD;
    float* Bh = Al + 128 * APAD;     // [GK][BPAD]
    float* Bl = Bh + GK * BPAD;

    const float* __restrict__ Ain = A ? A : (const float*)g_ao;
    const int m0 = blockIdx.x * GM, n0 = blockIdx.y * GN;
    const int t = threadIdx.x, warp = t >> 5, lane = t & 31;
    const int g = lane >> 2, tig = lane & 3;
    const int wm = (warp & 3) * 32, wn = (warp >> 2) * 32;

    const int am = t >> 3, ak = (t & 7) * 4;
    const int bk = t >> 4, bn = (t & 15) * 4;

    float4 aS[4], bS[2];
    #pragma unroll
    for (int i = 0; i < 4; i++)
        aS[i] = *(const float4*)&Ain[(size_t)(m0 + am + i*32) * D_MODEL + ak];
    #pragma unroll
    for (int i = 0; i < 2; i++)
        bS[i] = *(const float4*)&W[(size_t)(bk + i*16) * D_MODEL + n0 + bn];

    float acc[2][4][4] = {};

    for (int kt = 0; kt < D_MODEL / GK; kt++) {
        #pragma unroll
        for (int i = 0; i < 4; i++) {
            float4 v = aS[i], h, l;
            h.x = __uint_as_float(f2tf32(v.x)); l.x = __uint_as_float(f2tf32(v.x - h.x));
            h.y = __uint_as_float(f2tf32(v.y)); l.y = __uint_as_float(f2tf32(v.y - h.y));
            h.z = __uint_as_float(f2tf32(v.z)); l.z = __uint_as_float(f2tf32(v.z - h.z));
            h.w = __uint_as_float(f2tf32(v.w)); l.w = __uint_as_float(f2tf32(v.w - h.w));
            *(float4*)&Ah[(am + i*32) * APAD + ak] = h;
            *(float4*)&Al[(am + i*32) * APAD + ak] = l;
        }
        #pragma unroll
        for (int i = 0; i < 2; i++) {
            float4 v = bS[i], h, l;
            h.x = __uint_as_float(f2tf32(v.x)); l.x = __uint_as_float(f2tf32(v.x - h.x));
            h.y = __uint_as_float(f2tf32(v.y)); l.y = __uint_as_float(f2tf32(v.y - h.y));
            h.z = __uint_as_float(f2tf32(v.z)); l.z = __uint_as_float(f2tf32(v.z - h.z));
            h.w = __uint_as_float(f2tf32(v.w)); l.w = __uint_as_float(f2tf32(v.w - h.w));
            *(float4*)&Bh[(bk + i*16) * BPAD + bn] = h;
            *(float4*)&Bl[(bk + i*16) * BPAD + bn] = l;
        }
        __syncthreads();

        if (kt + 1 < D_MODEL / GK) {
            const int k0 = (kt + 1) * GK;
            #pragma unroll
            for (int i = 0; i < 4; i++)
                aS[i] = *(const float4*)&Ain[(size_t)(m0 + am + i*32) * D_MODEL + k0 + ak];
            #pragma unroll
            for (int i = 0; i < 2; i++)
                bS[i] = *(const float4*)&W[(size_t)(k0 + bk + i*16) * D_MODEL + n0 + bn];
        }

        #pragma unroll
        for (int kk = 0; kk < 4; kk++) {
            uint32_t afh[2][4], afl[2][4];
            #pragma unroll
            for (int mi = 0; mi < 2; mi++) {
                const int r0 = (wm + mi*16 + g) * APAD + kk*8 + tig;
                const int r1 = r0 + 8 * APAD;
                afh[mi][0] = __float_as_uint(Ah[r0]);
                afh[mi][1] = __float_as_uint(Ah[r1]);
                afh[mi][2] = __float_as_uint(Ah[r0 + 4]);
                afh[mi][3] = __float_as_uint(Ah[r1 + 4]);
                afl[mi][0] = __float_as_uint(Al[r0]);
                afl[mi][1] = __float_as_uint(Al[r1]);
                afl[mi][2] = __float_as_uint(Al[r0 + 4]);
                afl[mi][3] = __float_as_uint(Al[r1 + 4]);
            }
            uint32_t bfh[4][2], bfl[4][2];
            #pragma unroll
            for (int nt = 0; nt < 4; nt++) {
                const int r = (kk*8 + tig) * BPAD + wn + nt*8 + g;
                bfh[nt][0] = __float_as_uint(Bh[r]);
                bfh[nt][1] = __float_as_uint(Bh[r + 4*BPAD]);
                bfl[nt][0] = __float_as_uint(Bl[r]);
                bfl[nt][1] = __float_as_uint(Bl[r + 4*BPAD]);
            }
            #pragma unroll
            for (int mi = 0; mi < 2; mi++)
                #pragma unroll
                for (int nt = 0; nt < 4; nt++) {
                    mma_tf32(acc[mi][nt], afh[mi][0], afh[mi][1], afh[mi][2], afh[mi][3],
                             bfh[nt][0], bfh[nt][1]);
                    mma_tf32(acc[mi][nt], afh[mi][0], afh[mi][1], afh[mi][2], afh[mi][3],
                             bfl[nt][0], bfl[nt][1]);
                    mma_tf32(acc[mi][nt], afl[mi][0], afl[mi][1], afl[mi][2], afl[mi][3],
                             bfh[nt][0], bfh[nt][1]);
                }
        }
        __syncthreads();
    }

    #pragma unroll
    for (int mi = 0; mi < 2; mi++) {
        #pragma unroll
        for (int nt = 0; nt < 4; nt++) {
            const int col = wn + nt*8 + 2*tig;
            const float b0 = bias[n0 + col];
            const float b1 = bias[n0 + col + 1];
            const int mA = m0 + wm + mi*16 + g;
            const int mB = mA + 8;
            float2 vA = { acc[mi][nt][0] + b0, acc[mi][nt][1] + b1 };
            float2 vB = { acc[mi][nt][2] + b0, acc[mi][nt][3] + b1 };
            if (mode == 3) {
                *(float2*)&outp[(size_t)mA * D_MODEL + n0 + col] = vA;
                *(float2*)&outp[(size_t)mB * D_MODEL + n0 + col] = vB;
            } else {
                float* o = (mode == 0) ? g_q : (mode == 1) ? g_k : g_v;
                const int h = n0 >> 6;
                const size_t iA = (((size_t)((mA >> 11) * NHEADS + h) * SEQ)
                                   + (mA & 2047)) * DK + col;
                const size_t iB = (((size_t)((mB >> 11) * NHEADS + h) * SEQ)
                                   + (mB & 2047)) * DK + col;
                *(float2*)&o[iA] = vA;
                *(float2*)&o[iB] = vB;
            }
        }
    }
}

// ---------------------------------------------------------------------------
// Tensor-core (tf32 HMMA) flash attention — R6 numerics, 12 warps per CTA.
// Block: 192 queries of one (b,h); 12 warps x 16 query rows. 384 threads ->
// 170-reg budget at 1 CTA/SM, 12 resident warps (was 8). SEQ%192!=0: last
// tile has 4 invalid warps (clamped loads, guarded writes).
// ---------------------------------------------------------------------------
#define KPAD 68
#define VPAD 72
#define PPAD 68
#define QWARPS 12
#define TQ (QWARPS*16)          // 192 queries per block
#define NQT ((SEQ + TQ - 1) / TQ)   // 11
#define ATTN_SMEM_BYTES ((64*KPAD + 64*VPAD + QWARPS*16*PPAD) * 4)  // 88064

__global__ __launch_bounds__(384) void flash_attn_tc() {
    extern __shared__ uint32_t smem_u[];
    uint32_t* Ksu = smem_u;                       // [64][KPAD]
    uint32_t* Vsu = smem_u + 64 * KPAD;           // [64][VPAD]
    float*    Psb = (float*)(smem_u + 64 * KPAD + 64 * VPAD); // QWARPS x [16][PPAD]

    const int t    = threadIdx.x;
    const int warp = t >> 5;
    const int lane = t & 31;
    const int g    = lane >> 2;
    const int tig  = lane & 3;

    const int qt = blockIdx.x, h = blockIdx.y, b = blockIdx.z;
    const size_t headBase = (size_t)(b * NHEADS + h) * SEQ * DK;
    const float* __restrict__ kp = g_k + headBase;
    const float* __restrict__ vp = g_v + headBase;

    const float qscale = 0.125f * 1.4426950408889634f;
    const int row_a  = qt * TQ + warp * 16 + g;        // may exceed SEQ on last tile
    const int valid  = (qt * TQ + warp * 16) < SEQ;    // per-warp uniform
    const int row_ld = valid ? row_a : g;              // clamp loads for dead warps
    const float* __restrict__ qa = g_q + headBase + (size_t)row_ld * DK;
    const float* __restrict__ qb = qa + 8 * DK;

    uint32_t qf[8][4];
    #pragma unroll
    for (int ks = 0; ks < 8; ks++) {
        const int c0 = 8 * ks + tig;
        qf[ks][0] = f2tf32(qa[c0]     * qscale);
        qf[ks][1] = f2tf32(qb[c0]     * qscale);
        qf[ks][2] = f2tf32(qa[c0 + 4] * qscale);
        qf[ks][3] = f2tf32(qb[c0 + 4] * qscale);
    }

    float o[8][4];
    #pragma unroll
    for (int nt = 0; nt < 8; nt++)
        #pragma unroll
        for (int c = 0; c < 4; c++) o[nt][c] = 0.f;
    float m0 = -1e30f, m1 = -1e30f, l0 = 0.f, l1 = 0.f;

    float* Pw = Psb + warp * 16 * PPAD;

    for (int k0 = 0; k0 < SEQ; k0 += 64) {
        // ---- load K/V tile (1024 float4 slots over 384 threads) ----
        for (int fi = t; fi < 1024; fi += 384) {
            const int r = fi >> 4;
            const int c = (fi & 15) * 4;
            float4 kv = *(const float4*)&kp[(size_t)(k0 + r) * DK + c];
            float4 vv = *(const float4*)&vp[(size_t)(k0 + r) * DK + c];
            uint4 ku = { f2tf32(kv.x), f2tf32(kv.y), f2tf32(kv.z), f2tf32(kv.w) };
            uint4 vu = { f2tf32(vv.x), f2tf32(vv.y), f2tf32(vv.z), f2tf32(vv.w) };
            *(uint4*)&Ksu[r * KPAD + c] = ku;
            *(uint4*)&Vsu[r * VPAD + c] = vu;
        }
        __syncthreads();

        // ---- S = Q K^T ----
        float s[8][4];
        #pragma unroll
        for (int nt = 0; nt < 8; nt++) {
            #pragma unroll
            for (int c = 0; c < 4; c++) s[nt][c] = 0.f;
            const int key = nt * 8 + g;
            #pragma unroll
            for (int ks = 0; ks < 8; ks++) {
                const int d = ks * 8 + tig;
                uint32_t b0 = Ksu[key * KPAD + d];
                uint32_t b1 = Ksu[key * KPAD + d + 4];
                mma_tf32(s[nt], qf[ks][0], qf[ks][1], qf[ks][2], qf[ks][3], b0, b1);
            }
        }

        // ---- online softmax (base-2) ----
        float t0 = -1e30f, t1 = -1e30f;
        #pragma unroll
        for (int nt = 0; nt < 8; nt++) {
            t0 = fmaxf(t0, fmaxf(s[nt][0], s[nt][1]));
            t1 = fmaxf(t1, fmaxf(s[nt][2], s[nt][3]));
        }
        t0 = fmaxf(t0, __shfl_xor_sync(0xffffffffu, t0, 1));
        t0 = fmaxf(t0, __shfl_xor_sync(0xffffffffu, t0, 2));
        t1 = fmaxf(t1, __shfl_xor_sync(0xffffffffu, t1, 1));
        t1 = fmaxf(t1, __shfl_xor_sync(0xffffffffu, t1, 2));
        const float nm0 = fmaxf(m0, t0), nm1 = fmaxf(m1, t1);
        const float cr0 = fexp2(m0 - nm0), cr1 = fexp2(m1 - nm1);

        float p0 = 0.f, p1 = 0.f;
        #pragma unroll
        for (int nt = 0; nt < 8; nt++) {
            s[nt][0] = fexp2(s[nt][0] - nm0);
            s[nt][1] = fexp2(s[nt][1] - nm0);
            s[nt][2] = fexp2(s[nt][2] - nm1);
            s[nt][3] = fexp2(s[nt][3] - nm1);
            p0 += s[nt][0] + s[nt][1];
            p1 += s[nt][2] + s[nt][3];
        }
        p0 += __shfl_xor_sync(0xffffffffu, p0, 1);
        p0 += __shfl_xor_sync(0xffffffffu, p0, 2);
        p1 += __shfl_xor_sync(0xffffffffu, p1, 1);
        p1 += __shfl_xor_sync(0xffffffffu, p1, 2);
        l0 = l0 * cr0 + p0;
        l1 = l1 * cr1 + p1;
        m0 = nm0; m1 = nm1;

        #pragma unroll
        for (int nt = 0; nt < 8; nt++) {
            o[nt][0] *= cr0; o[nt][1] *= cr0;
            o[nt][2] *= cr1; o[nt][3] *= cr1;
        }

        // ---- P -> per-warp smem (tf32) ----
        #pragma unroll
        for (int nt = 0; nt < 8; nt++) {
            const int col = nt * 8 + 2 * tig;
            float2 lo = { __uint_as_float(f2tf32(s[nt][0])),
                          __uint_as_float(f2tf32(s[nt][1])) };
            float2 hi = { __uint_as_float(f2tf32(s[nt][2])),
                          __uint_as_float(f2tf32(s[nt][3])) };
            *(float2*)&Pw[g * PPAD + col]       = lo;
            *(float2*)&Pw[(g + 8) * PPAD + col] = hi;
        }
        __syncwarp();

        // ---- O += P V (A-frags per-ks: low reg pressure, 8 indep chains) ----
        #pragma unroll
        for (int ks = 0; ks < 8; ks++) {
            const int kk = ks * 8 + tig;
            const uint32_t a0 = __float_as_uint(Pw[g * PPAD + kk]);
            const uint32_t a1 = __float_as_uint(Pw[(g + 8) * PPAD + kk]);
            const uint32_t a2 = __float_as_uint(Pw[g * PPAD + kk + 4]);
            const uint32_t a3 = __float_as_uint(Pw[(g + 8) * PPAD + kk + 4]);
            const int key = ks * 8 + tig;
            #pragma unroll
            for (int nt = 0; nt < 8; nt++) {
                const int dcol = nt * 8 + g;
                uint32_t b0 = Vsu[key * VPAD + dcol];
                uint32_t b1 = Vsu[(key + 4) * VPAD + dcol];
                mma_tf32(o[nt], a0, a1, a2, a3, b0, b1);
            }
        }
        __syncthreads();
    }

    if (valid) {
        const float inv0 = 1.0f / l0, inv1 = 1.0f / l1;
        float* oa = g_ao + (size_t)(b * SEQ + row_a) * D_MODEL + h * DK;
        float* ob = oa + (size_t)8 * D_MODEL;
        #pragma unroll
        for (int nt = 0; nt < 8; nt++) {
            const int col = nt * 8 + 2 * tig;
            float2 lo = { o[nt][0] * inv0, o[nt][1] * inv0 };
            float2 hi = { o[nt][2] * inv1, o[nt][3] * inv1 };
            *(float2*)&oa[col] = lo;
            *(float2*)&ob[col] = hi;
        }
    }
}

extern "C" void kernel_launch(void* const* d_in, const int* in_sizes, int n_in,
                              void* d_out, int out_size) {
    const float* q  = (const float*)d_in[0];
    const float* k  = (const float*)d_in[1];
    const float* v  = (const float*)d_in[2];
    const float* Wq = (const float*)d_in[3];
    const float* bq = (const float*)d_in[4];
    const float* Wk = (const float*)d_in[5];
    const float* bk = (const float*)d_in[6];
    const float* Wv = (const float*)d_in[7];
    const float* bv = (const float*)d_in[8];
    const float* Wo = (const float*)d_in[9];
    const float* bo = (const float*)d_in[10];
    float* out = (float*)d_out;

    cudaFuncSetAttribute(gemm_tc,
                         cudaFuncAttributeMaxDynamicSharedMemorySize, GEMM_SMEM);
    cudaFuncSetAttribute(flash_attn_tc,
                         cudaFuncAttributeMaxDynamicSharedMemorySize,
                         ATTN_SMEM_BYTES);

    dim3 gg(MTOT / GM, D_MODEL / GN);     // 32 x 12
    gemm_tc<<<gg, 256, GEMM_SMEM>>>(q, Wq, bq, nullptr, 0);
    gemm_tc<<<gg, 256, GEMM_SMEM>>>(k, Wk, bk, nullptr, 1);
    gemm_tc<<<gg, 256, GEMM_SMEM>>>(v, Wv, bv, nullptr, 2);

    dim3 ga(NQT, NHEADS, BATCH);          // 11 x 12 x 2
    flash_attn_tc<<<ga, 384, ATTN_SMEM_BYTES>>>();

    dim3 go(MTOT / GM, D_MODEL / GN);     // 32 x 12
    gemm_tc<<<go, 256, GEMM_SMEM>>>(nullptr, Wo, bo, out, 3);
}

// round 14
// speedup vs baseline: 1.7952x; 1.0385x over previous
#include <cuda_runtime.h>
#include <cstdint>

#define D_MODEL 768
#define NHEADS  12
#define DK      64
#define BATCH   2
#define SEQ     2048
#define MTOT    (BATCH*SEQ)   // 4096

// Scratch (device globals: allocation-free, harness-safe)
__device__ float g_q [BATCH*NHEADS*SEQ*DK];   // [B,H,S,dk]
__device__ float g_k [BATCH*NHEADS*SEQ*DK];
__device__ float g_v [BATCH*NHEADS*SEQ*DK];
__device__ float g_ao[MTOT*D_MODEL];          // [B,S,D] attention output

__device__ __forceinline__ uint32_t f2tf32(float x) {
    uint32_t r;
    asm("cvt.rna.tf32.f32 %0, %1;" : "=r"(r) : "f"(x));
    return r;
}
__device__ __forceinline__ float fexp2(float x) {
    float y;
    asm("ex2.approx.ftz.f32 %0, %1;" : "=f"(y) : "f"(x));
    return y;
}
__device__ __forceinline__ void mma_tf32(float c[4],
        uint32_t a0, uint32_t a1, uint32_t a2, uint32_t a3,
        uint32_t b0, uint32_t b1) {
    asm volatile(
        "mma.sync.aligned.m16n8k8.row.col.f32.tf32.tf32.f32 "
        "{%0,%1,%2,%3}, {%4,%5,%6,%7}, {%8,%9}, {%0,%1,%2,%3};"
        : "+f"(c[0]), "+f"(c[1]), "+f"(c[2]), "+f"(c[3])
        : "r"(a0), "r"(a1), "r"(a2), "r"(a3), "r"(b0), "r"(b1));
}

// ---------------------------------------------------------------------------
// 3xTF32 tensor-core GEMM with bias (fp32-accurate) — R6 version (proven).
// Block: 128(M) x 64(N), BK=32. 8 warps in 4(m) x 2(n); warp tile 32x32.
// mode 0/1/2: scatter into g_q/g_k/g_v head-split. mode 3: row-major outp.
// A==nullptr -> read from g_ao.
// ---------------------------------------------------------------------------
#define GM 128
#define GN 64
#define GK 32
#define APAD 36
#define BPAD 72
#define GEMM_SMEM ((2*128*APAD + 2*GK*BPAD) * 4)   // 55296 B

__global__ __launch_bounds__(256, 2) void gemm_tc(
        const float* __restrict__ A, const float* __restrict__ W,
        const float* __restrict__ bias, float* __restrict__ outp, int mode) {
    extern __shared__ float sm[];
    float* Ah = sm;                  // [128][APAD]
    float* Al = Ah + 128 * APAD;
    float* Bh = Al + 128 * APAD;     // [GK][BPAD]
    float* Bl = Bh + GK * BPAD;

    const float* __restrict__ Ain = A ? A : (const float*)g_ao;
    const int m0 = blockIdx.x * GM, n0 = blockIdx.y * GN;
    const int t = threadIdx.x, warp = t >> 5, lane = t & 31;
    const int g = lane >> 2, tig = lane & 3;
    const int wm = (warp & 3) * 32, wn = (warp >> 2) * 32;

    const int am = t >> 3, ak = (t & 7) * 4;
    const int bk = t >> 4, bn = (t & 15) * 4;

    float4 aS[4], bS[2];
    #pragma unroll
    for (int i = 0; i < 4; i++)
        aS[i] = *(const float4*)&Ain[(size_t)(m0 + am + i*32) * D_MODEL + ak];
    #pragma unroll
    for (int i = 0; i < 2; i++)
        bS[i] = *(const float4*)&W[(size_t)(bk + i*16) * D_MODEL + n0 + bn];

    float acc[2][4][4] = {};

    for (int kt = 0; kt < D_MODEL / GK; kt++) {
        #pragma unroll
        for (int i = 0; i < 4; i++) {
            float4 v = aS[i], h, l;
            h.x = __uint_as_float(f2tf32(v.x)); l.x = __uint_as_float(f2tf32(v.x - h.x));
            h.y = __uint_as_float(f2tf32(v.y)); l.y = __uint_as_float(f2tf32(v.y - h.y));
            h.z = __uint_as_float(f2tf32(v.z)); l.z = __uint_as_float(f2tf32(v.z - h.z));
            h.w = __uint_as_float(f2tf32(v.w)); l.w = __uint_as_float(f2tf32(v.w - h.w));
            *(float4*)&Ah[(am + i*32) * APAD + ak] = h;
            *(float4*)&Al[(am + i*32) * APAD + ak] = l;
        }
        #pragma unroll
        for (int i = 0; i < 2; i++) {
            float4 v = bS[i], h, l;
            h.x = __uint_as_float(f2tf32(v.x)); l.x = __uint_as_float(f2tf32(v.x - h.x));
            h.y = __uint_as_float(f2tf32(v.y)); l.y = __uint_as_float(f2tf32(v.y - h.y));
            h.z = __uint_as_float(f2tf32(v.z)); l.z = __uint_as_float(f2tf32(v.z - h.z));
            h.w = __uint_as_float(f2tf32(v.w)); l.w = __uint_as_float(f2tf32(v.w - h.w));
            *(float4*)&Bh[(bk + i*16) * BPAD + bn] = h;
            *(float4*)&Bl[(bk + i*16) * BPAD + bn] = l;
        }
        __syncthreads();

        if (kt + 1 < D_MODEL / GK) {
            const int k0 = (kt + 1) * GK;
            #pragma unroll
            for (int i = 0; i < 4; i++)
                aS[i] = *(const float4*)&Ain[(size_t)(m0 + am + i*32) * D_MODEL + k0 + ak];
            #pragma unroll
            for (int i = 0; i < 2; i++)
                bS[i] = *(const float4*)&W[(size_t)(k0 + bk + i*16) * D_MODEL + n0 + bn];
        }

        #pragma unroll
        for (int kk = 0; kk < 4; kk++) {
            uint32_t afh[2][4], afl[2][4];
            #pragma unroll
            for (int mi = 0; mi < 2; mi++) {
                const int r0 = (wm + mi*16 + g) * APAD + kk*8 + tig;
                const int r1 = r0 + 8 * APAD;
                afh[mi][0] = __float_as_uint(Ah[r0]);
                afh[mi][1] = __float_as_uint(Ah[r1]);
                afh[mi][2] = __float_as_uint(Ah[r0 + 4]);
                afh[mi][3] = __float_as_uint(Ah[r1 + 4]);
                afl[mi][0] = __float_as_uint(Al[r0]);
                afl[mi][1] = __float_as_uint(Al[r1]);
                afl[mi][2] = __float_as_uint(Al[r0 + 4]);
                afl[mi][3] = __float_as_uint(Al[r1 + 4]);
            }
            uint32_t bfh[4][2], bfl[4][2];
            #pragma unroll
            for (int nt = 0; nt < 4; nt++) {
                const int r = (kk*8 + tig) * BPAD + wn + nt*8 + g;
                bfh[nt][0] = __float_as_uint(Bh[r]);
                bfh[nt][1] = __float_as_uint(Bh[r + 4*BPAD]);
                bfl[nt][0] = __float_as_uint(Bl[r]);
                bfl[nt][1] = __float_as_uint(Bl[r + 4*BPAD]);
            }
            #pragma unroll
            for (int mi = 0; mi < 2; mi++)
                #pragma unroll
                for (int nt = 0; nt < 4; nt++) {
                    mma_tf32(acc[mi][nt], afh[mi][0], afh[mi][1], afh[mi][2], afh[mi][3],
                             bfh[nt][0], bfh[nt][1]);
                    mma_tf32(acc[mi][nt], afh[mi][0], afh[mi][1], afh[mi][2], afh[mi][3],
                             bfl[nt][0], bfl[nt][1]);
                    mma_tf32(acc[mi][nt], afl[mi][0], afl[mi][1], afl[mi][2], afl[mi][3],
                             bfh[nt][0], bfh[nt][1]);
                }
        }
        __syncthreads();
    }

    #pragma unroll
    for (int mi = 0; mi < 2; mi++) {
        #pragma unroll
        for (int nt = 0; nt < 4; nt++) {
            const int col = wn + nt*8 + 2*tig;
            const float b0 = bias[n0 + col];
            const float b1 = bias[n0 + col + 1];
            const int mA = m0 + wm + mi*16 + g;
            const int mB = mA + 8;
            float2 vA = { acc[mi][nt][0] + b0, acc[mi][nt][1] + b1 };
            float2 vB = { acc[mi][nt][2] + b0, acc[mi][nt][3] + b1 };
            if (mode == 3) {
                *(float2*)&outp[(size_t)mA * D_MODEL + n0 + col] = vA;
                *(float2*)&outp[(size_t)mB * D_MODEL + n0 + col] = vB;
            } else {
                float* o = (mode == 0) ? g_q : (mode == 1) ? g_k : g_v;
                const int h = n0 >> 6;
                const size_t iA = (((size_t)((mA >> 11) * NHEADS + h) * SEQ)
                                   + (mA & 2047)) * DK + col;
                const size_t iB = (((size_t)((mB >> 11) * NHEADS + h) * SEQ)
                                   + (mB & 2047)) * DK + col;
                *(float2*)&o[iA] = vA;
                *(float2*)&o[iB] = vB;
            }
        }
    }
}

// ---------------------------------------------------------------------------
// Tensor-core (tf32 HMMA) flash attention — reg-lean PV path (130 regs at
// 384T in R13) now capped to 128 with __launch_bounds__(256,2): 2 CTA/SM,
// 16 resident warps, independent-CTA progress across barriers.
// Block: 128 queries of one (b,h); 8 warps x 16 query rows.
// ---------------------------------------------------------------------------
#define KPAD 68
#define VPAD 72
#define PPAD 68
#define QWARPS 8
#define TQ (QWARPS*16)              // 128 queries per block
#define ATTN_SMEM_BYTES ((64*KPAD + 64*VPAD + QWARPS*16*PPAD) * 4)  // 70656

__global__ __launch_bounds__(256, 2) void flash_attn_tc() {
    extern __shared__ uint32_t smem_u[];
    uint32_t* Ksu = smem_u;                       // [64][KPAD]
    uint32_t* Vsu = smem_u + 64 * KPAD;           // [64][VPAD]
    float*    Psb = (float*)(smem_u + 64 * KPAD + 64 * VPAD); // QWARPS x [16][PPAD]

    const int t    = threadIdx.x;
    const int warp = t >> 5;
    const int lane = t & 31;
    const int g    = lane >> 2;
    const int tig  = lane & 3;

    const int qt = blockIdx.x, h = blockIdx.y, b = blockIdx.z;
    const size_t headBase = (size_t)(b * NHEADS + h) * SEQ * DK;
    const float* __restrict__ kp = g_k + headBase;
    const float* __restrict__ vp = g_v + headBase;

    const float qscale = 0.125f * 1.4426950408889634f;
    const int row_a = qt * TQ + warp * 16 + g;
    const float* __restrict__ qa = g_q + headBase + (size_t)row_a * DK;
    const float* __restrict__ qb = qa + 8 * DK;

    uint32_t qf[8][4];
    #pragma unroll
    for (int ks = 0; ks < 8; ks++) {
        const int c0 = 8 * ks + tig;
        qf[ks][0] = f2tf32(qa[c0]     * qscale);
        qf[ks][1] = f2tf32(qb[c0]     * qscale);
        qf[ks][2] = f2tf32(qa[c0 + 4] * qscale);
        qf[ks][3] = f2tf32(qb[c0 + 4] * qscale);
    }

    float o[8][4];
    #pragma unroll
    for (int nt = 0; nt < 8; nt++)
        #pragma unroll
        for (int c = 0; c < 4; c++) o[nt][c] = 0.f;
    float m0 = -1e30f, m1 = -1e30f, l0 = 0.f, l1 = 0.f;

    float* Pw = Psb + warp * 16 * PPAD;

    for (int k0 = 0; k0 < SEQ; k0 += 64) {
        // ---- load K/V tile (1024 float4 slots over 256 threads) ----
        #pragma unroll
        for (int i = 0; i < 4; i++) {
            const int fi = t + i * 256;
            const int r  = fi >> 4;
            const int c  = (fi & 15) * 4;
            float4 kv = *(const float4*)&kp[(size_t)(k0 + r) * DK + c];
            float4 vv = *(const float4*)&vp[(size_t)(k0 + r) * DK + c];
            uint4 ku = { f2tf32(kv.x), f2tf32(kv.y), f2tf32(kv.z), f2tf32(kv.w) };
            uint4 vu = { f2tf32(vv.x), f2tf32(vv.y), f2tf32(vv.z), f2tf32(vv.w) };
            *(uint4*)&Ksu[r * KPAD + c] = ku;
            *(uint4*)&Vsu[r * VPAD + c] = vu;
        }
        __syncthreads();

        // ---- S = Q K^T ----
        float s[8][4];
        #pragma unroll
        for (int nt = 0; nt < 8; nt++) {
            #pragma unroll
            for (int c = 0; c < 4; c++) s[nt][c] = 0.f;
            const int key = nt * 8 + g;
            #pragma unroll
            for (int ks = 0; ks < 8; ks++) {
                const int d = ks * 8 + tig;
                uint32_t b0 = Ksu[key * KPAD + d];
                uint32_t b1 = Ksu[key * KPAD + d + 4];
                mma_tf32(s[nt], qf[ks][0], qf[ks][1], qf[ks][2], qf[ks][3], b0, b1);
            }
        }

        // ---- online softmax (base-2) ----
        float t0 = -1e30f, t1 = -1e30f;
        #pragma unroll
        for (int nt = 0; nt < 8; nt++) {
            t0 = fmaxf(t0, fmaxf(s[nt][0], s[nt][1]));
            t1 = fmaxf(t1, fmaxf(s[nt][2], s[nt][3]));
        }
        t0 = fmaxf(t0, __shfl_xor_sync(0xffffffffu, t0, 1));
        t0 = fmaxf(t0, __shfl_xor_sync(0xffffffffu, t0, 2));
        t1 = fmaxf(t1, __shfl_xor_sync(0xffffffffu, t1, 1));
        t1 = fmaxf(t1, __shfl_xor_sync(0xffffffffu, t1, 2));
        const float nm0 = fmaxf(m0, t0), nm1 = fmaxf(m1, t1);
        const float cr0 = fexp2(m0 - nm0), cr1 = fexp2(m1 - nm1);

        float p0 = 0.f, p1 = 0.f;
        #pragma unroll
        for (int nt = 0; nt < 8; nt++) {
            s[nt][0] = fexp2(s[nt][0] - nm0);
            s[nt][1] = fexp2(s[nt][1] - nm0);
            s[nt][2] = fexp2(s[nt][2] - nm1);
            s[nt][3] = fexp2(s[nt][3] - nm1);
            p0 += s[nt][0] + s[nt][1];
            p1 += s[nt][2] + s[nt][3];
        }
        p0 += __shfl_xor_sync(0xffffffffu, p0, 1);
        p0 += __shfl_xor_sync(0xffffffffu, p0, 2);
        p1 += __shfl_xor_sync(0xffffffffu, p1, 1);
        p1 += __shfl_xor_sync(0xffffffffu, p1, 2);
        l0 = l0 * cr0 + p0;
        l1 = l1 * cr1 + p1;
        m0 = nm0; m1 = nm1;

        #pragma unroll
        for (int nt = 0; nt < 8; nt++) {
            o[nt][0] *= cr0; o[nt][1] *= cr0;
            o[nt][2] *= cr1; o[nt][3] *= cr1;
        }

        // ---- P -> per-warp smem (tf32) ----
        #pragma unroll
        for (int nt = 0; nt < 8; nt++) {
            const int col = nt * 8 + 2 * tig;
            float2 lo = { __uint_as_float(f2tf32(s[nt][0])),
                          __uint_as_float(f2tf32(s[nt][1])) };
            float2 hi = { __uint_as_float(f2tf32(s[nt][2])),
                          __uint_as_float(f2tf32(s[nt][3])) };
            *(float2*)&Pw[g * PPAD + col]       = lo;
            *(float2*)&Pw[(g + 8) * PPAD + col] = hi;
        }
        __syncwarp();

        // ---- O += P V (A-frags per-ks: reg-lean, 8 indep chains) ----
        #pragma unroll
        for (int ks = 0; ks < 8; ks++) {
            const int kk = ks * 8 + tig;
            const uint32_t a0 = __float_as_uint(Pw[g * PPAD + kk]);
            const uint32_t a1 = __float_as_uint(Pw[(g + 8) * PPAD + kk]);
            const uint32_t a2 = __float_as_uint(Pw[g * PPAD + kk + 4]);
            const uint32_t a3 = __float_as_uint(Pw[(g + 8) * PPAD + kk + 4]);
            const int key = ks * 8 + tig;
            #pragma unroll
            for (int nt = 0; nt < 8; nt++) {
                const int dcol = nt * 8 + g;
                uint32_t b0 = Vsu[key * VPAD + dcol];
                uint32_t b1 = Vsu[(key + 4) * VPAD + dcol];
                mma_tf32(o[nt], a0, a1, a2, a3, b0, b1);
            }
        }
        __syncthreads();
    }

    const float inv0 = 1.0f / l0, inv1 = 1.0f / l1;
    float* oa = g_ao + (size_t)(b * SEQ + row_a) * D_MODEL + h * DK;
    float* ob = oa + (size_t)8 * D_MODEL;
    #pragma unroll
    for (int nt = 0; nt < 8; nt++) {
        const int col = nt * 8 + 2 * tig;
        float2 lo = { o[nt][0] * inv0, o[nt][1] * inv0 };
        float2 hi = { o[nt][2] * inv1, o[nt][3] * inv1 };
        *(float2*)&oa[col] = lo;
        *(float2*)&ob[col] = hi;
    }
}

extern "C" void kernel_launch(void* const* d_in, const int* in_sizes, int n_in,
                              void* d_out, int out_size) {
    const float* q  = (const float*)d_in[0];
    const float* k  = (const float*)d_in[1];
    const float* v  = (const float*)d_in[2];
    const float* Wq = (const float*)d_in[3];
    const float* bq = (const float*)d_in[4];
    const float* Wk = (const float*)d_in[5];
    const float* bk = (const float*)d_in[6];
    const float* Wv = (const float*)d_in[7];
    const float* bv = (const float*)d_in[8];
    const float* Wo = (const float*)d_in[9];
    const float* bo = (const float*)d_in[10];
    float* out = (float*)d_out;

    cudaFuncSetAttribute(gemm_tc,
                         cudaFuncAttributeMaxDynamicSharedMemorySize, GEMM_SMEM);
    cudaFuncSetAttribute(flash_attn_tc,
                         cudaFuncAttributeMaxDynamicSharedMemorySize,
                         ATTN_SMEM_BYTES);

    dim3 gg(MTOT / GM, D_MODEL / GN);     // 32 x 12
    gemm_tc<<<gg, 256, GEMM_SMEM>>>(q, Wq, bq, nullptr, 0);
    gemm_tc<<<gg, 256, GEMM_SMEM>>>(k, Wk, bk, nullptr, 1);
    gemm_tc<<<gg, 256, GEMM_SMEM>>>(v, Wv, bv, nullptr, 2);

    dim3 ga(SEQ / TQ, NHEADS, BATCH);     // 16 x 12 x 2
    flash_attn_tc<<<ga, 256, ATTN_SMEM_BYTES>>>();

    dim3 go(MTOT / GM, D_MODEL / GN);     // 32 x 12
    gemm_tc<<<go, 256, GEMM_SMEM>>>(nullptr, Wo, bo, out, 3);
}

// round 15
// speedup vs baseline: 2.1546x; 1.2002x over previous
#include <cuda_runtime.h>
#include <cstdint>

#define D_MODEL 768
#define NHEADS  12
#define DK      64
#define BATCH   2
#define SEQ     2048
#define MTOT    (BATCH*SEQ)   // 4096

// Scratch (device globals: allocation-free, harness-safe)
__device__ float g_q [BATCH*NHEADS*SEQ*DK];   // [B,H,S,dk]
__device__ float g_k [BATCH*NHEADS*SEQ*DK];
__device__ float g_v [BATCH*NHEADS*SEQ*DK];
__device__ float g_ao[MTOT*D_MODEL];          // [B,S,D] attention output

__device__ __forceinline__ uint32_t f2tf32(float x) {
    uint32_t r;
    asm("cvt.rna.tf32.f32 %0, %1;" : "=r"(r) : "f"(x));
    return r;
}
__device__ __forceinline__ float fexp2(float x) {
    float y;
    asm("ex2.approx.ftz.f32 %0, %1;" : "=f"(y) : "f"(x));
    return y;
}
__device__ __forceinline__ void mma_tf32(float c[4],
        uint32_t a0, uint32_t a1, uint32_t a2, uint32_t a3,
        uint32_t b0, uint32_t b1) {
    asm volatile(
        "mma.sync.aligned.m16n8k8.row.col.f32.tf32.tf32.f32 "
        "{%0,%1,%2,%3}, {%4,%5,%6,%7}, {%8,%9}, {%0,%1,%2,%3};"
        : "+f"(c[0]), "+f"(c[1]), "+f"(c[2]), "+f"(c[3])
        : "r"(a0), "r"(a1), "r"(a2), "r"(a3), "r"(b0), "r"(b1));
}

// ---------------------------------------------------------------------------
// 2-term TF32 tensor-core GEMM with bias: A rounded once, W split hi/lo.
// acc += At*Bh + At*Bl = At*B (exact in B); residual = (A-At)*B ~1.2e-4 rel.
// Block: 128(M) x 64(N), BK=32. 8 warps in 4(m) x 2(n); warp tile 32x32.
// mode 0/1/2: scatter into g_q/g_k/g_v head-split. mode 3: row-major outp.
// A==nullptr -> read from g_ao.
// ---------------------------------------------------------------------------
#define GM 128
#define GN 64
#define GK 32
#define APAD 36
#define BPAD 72
#define GEMM_SMEM ((128*APAD + 2*GK*BPAD) * 4)   // 36864 B

__global__ __launch_bounds__(256, 2) void gemm_tc(
        const float* __restrict__ A, const float* __restrict__ W,
        const float* __restrict__ bias, float* __restrict__ outp, int mode) {
    extern __shared__ float sm[];
    float* At = sm;                  // [128][APAD]  (single tf32 plane)
    float* Bh = At + 128 * APAD;     // [GK][BPAD]
    float* Bl = Bh + GK * BPAD;

    const float* __restrict__ Ain = A ? A : (const float*)g_ao;
    const int m0 = blockIdx.x * GM, n0 = blockIdx.y * GN;
    const int t = threadIdx.x, warp = t >> 5, lane = t & 31;
    const int g = lane >> 2, tig = lane & 3;
    const int wm = (warp & 3) * 32, wn = (warp >> 2) * 32;

    const int am = t >> 3, ak = (t & 7) * 4;
    const int bk = t >> 4, bn = (t & 15) * 4;

    float4 aS[4], bS[2];
    #pragma unroll
    for (int i = 0; i < 4; i++)
        aS[i] = *(const float4*)&Ain[(size_t)(m0 + am + i*32) * D_MODEL + ak];
    #pragma unroll
    for (int i = 0; i < 2; i++)
        bS[i] = *(const float4*)&W[(size_t)(bk + i*16) * D_MODEL + n0 + bn];

    float acc[2][4][4] = {};

    for (int kt = 0; kt < D_MODEL / GK; kt++) {
        // ---- stage A (single tf32) ----
        #pragma unroll
        for (int i = 0; i < 4; i++) {
            float4 v = aS[i], h;
            h.x = __uint_as_float(f2tf32(v.x));
            h.y = __uint_as_float(f2tf32(v.y));
            h.z = __uint_as_float(f2tf32(v.z));
            h.w = __uint_as_float(f2tf32(v.w));
            *(float4*)&At[(am + i*32) * APAD + ak] = h;
        }
        // ---- stage B hi/lo split (exact) ----
        #pragma unroll
        for (int i = 0; i < 2; i++) {
            float4 v = bS[i], h, l;
            h.x = __uint_as_float(f2tf32(v.x)); l.x = __uint_as_float(f2tf32(v.x - h.x));
            h.y = __uint_as_float(f2tf32(v.y)); l.y = __uint_as_float(f2tf32(v.y - h.y));
            h.z = __uint_as_float(f2tf32(v.z)); l.z = __uint_as_float(f2tf32(v.z - h.z));
            h.w = __uint_as_float(f2tf32(v.w)); l.w = __uint_as_float(f2tf32(v.w - h.w));
            *(float4*)&Bh[(bk + i*16) * BPAD + bn] = h;
            *(float4*)&Bl[(bk + i*16) * BPAD + bn] = l;
        }
        __syncthreads();

        // ---- prefetch next tile ----
        if (kt + 1 < D_MODEL / GK) {
            const int k0 = (kt + 1) * GK;
            #pragma unroll
            for (int i = 0; i < 4; i++)
                aS[i] = *(const float4*)&Ain[(size_t)(m0 + am + i*32) * D_MODEL + k0 + ak];
            #pragma unroll
            for (int i = 0; i < 2; i++)
                bS[i] = *(const float4*)&W[(size_t)(k0 + bk + i*16) * D_MODEL + n0 + bn];
        }

        // ---- 2 MMAs per fragment pair ----
        #pragma unroll
        for (int kk = 0; kk < 4; kk++) {
            uint32_t af[2][4];
            #pragma unroll
            for (int mi = 0; mi < 2; mi++) {
                const int r0 = (wm + mi*16 + g) * APAD + kk*8 + tig;
                const int r1 = r0 + 8 * APAD;
                af[mi][0] = __float_as_uint(At[r0]);
                af[mi][1] = __float_as_uint(At[r1]);
                af[mi][2] = __float_as_uint(At[r0 + 4]);
                af[mi][3] = __float_as_uint(At[r1 + 4]);
            }
            uint32_t bfh[4][2], bfl[4][2];
            #pragma unroll
            for (int nt = 0; nt < 4; nt++) {
                const int r = (kk*8 + tig) * BPAD + wn + nt*8 + g;
                bfh[nt][0] = __float_as_uint(Bh[r]);
                bfh[nt][1] = __float_as_uint(Bh[r + 4*BPAD]);
                bfl[nt][0] = __float_as_uint(Bl[r]);
                bfl[nt][1] = __float_as_uint(Bl[r + 4*BPAD]);
            }
            #pragma unroll
            for (int mi = 0; mi < 2; mi++)
                #pragma unroll
                for (int nt = 0; nt < 4; nt++) {
                    mma_tf32(acc[mi][nt], af[mi][0], af[mi][1], af[mi][2], af[mi][3],
                             bfh[nt][0], bfh[nt][1]);
                    mma_tf32(acc[mi][nt], af[mi][0], af[mi][1], af[mi][2], af[mi][3],
                             bfl[nt][0], bfl[nt][1]);
                }
        }
        __syncthreads();
    }

    #pragma unroll
    for (int mi = 0; mi < 2; mi++) {
        #pragma unroll
        for (int nt = 0; nt < 4; nt++) {
            const int col = wn + nt*8 + 2*tig;
            const float b0 = bias[n0 + col];
            const float b1 = bias[n0 + col + 1];
            const int mA = m0 + wm + mi*16 + g;
            const int mB = mA + 8;
            float2 vA = { acc[mi][nt][0] + b0, acc[mi][nt][1] + b1 };
            float2 vB = { acc[mi][nt][2] + b0, acc[mi][nt][3] + b1 };
            if (mode == 3) {
                *(float2*)&outp[(size_t)mA * D_MODEL + n0 + col] = vA;
                *(float2*)&outp[(size_t)mB * D_MODEL + n0 + col] = vB;
            } else {
                float* o = (mode == 0) ? g_q : (mode == 1) ? g_k : g_v;
                const int h = n0 >> 6;
                const size_t iA = (((size_t)((mA >> 11) * NHEADS + h) * SEQ)
                                   + (mA & 2047)) * DK + col;
                const size_t iB = (((size_t)((mB >> 11) * NHEADS + h) * SEQ)
                                   + (mB & 2047)) * DK + col;
                *(float2*)&o[iA] = vA;
                *(float2*)&o[iB] = vB;
            }
        }
    }
}

// ---------------------------------------------------------------------------
// Tensor-core (tf32 HMMA) flash attention — R14 version (proven, 250us):
// reg-lean PV path, __launch_bounds__(256,2), 2 CTA/SM, 16 resident warps.
// Block: 128 queries of one (b,h); 8 warps x 16 query rows.
// ---------------------------------------------------------------------------
#define KPAD 68
#define VPAD 72
#define PPAD 68
#define QWARPS 8
#define TQ (QWARPS*16)              // 128 queries per block
#define ATTN_SMEM_BYTES ((64*KPAD + 64*VPAD + QWARPS*16*PPAD) * 4)  // 70656

__global__ __launch_bounds__(256, 2) void flash_attn_tc() {
    extern __shared__ uint32_t smem_u[];
    uint32_t* Ksu = smem_u;                       // [64][KPAD]
    uint32_t* Vsu = smem_u + 64 * KPAD;           // [64][VPAD]
    float*    Psb = (float*)(smem_u + 64 * KPAD + 64 * VPAD); // QWARPS x [16][PPAD]

    const int t    = threadIdx.x;
    const int warp = t >> 5;
    const int lane = t & 31;
    const int g    = lane >> 2;
    const int tig  = lane & 3;

    const int qt = blockIdx.x, h = blockIdx.y, b = blockIdx.z;
    const size_t headBase = (size_t)(b * NHEADS + h) * SEQ * DK;
    const float* __restrict__ kp = g_k + headBase;
    const float* __restrict__ vp = g_v + headBase;

    const float qscale = 0.125f * 1.4426950408889634f;
    const int row_a = qt * TQ + warp * 16 + g;
    const float* __restrict__ qa = g_q + headBase + (size_t)row_a * DK;
    const float* __restrict__ qb = qa + 8 * DK;

    uint32_t qf[8][4];
    #pragma unroll
    for (int ks = 0; ks < 8; ks++) {
        const int c0 = 8 * ks + tig;
        qf[ks][0] = f2tf32(qa[c0]     * qscale);
        qf[ks][1] = f2tf32(qb[c0]     * qscale);
        qf[ks][2] = f2tf32(qa[c0 + 4] * qscale);
        qf[ks][3] = f2tf32(qb[c0 + 4] * qscale);
    }

    float o[8][4];
    #pragma unroll
    for (int nt = 0; nt < 8; nt++)
        #pragma unroll
        for (int c = 0; c < 4; c++) o[nt][c] = 0.f;
    float m0 = -1e30f, m1 = -1e30f, l0 = 0.f, l1 = 0.f;

    float* Pw = Psb + warp * 16 * PPAD;

    for (int k0 = 0; k0 < SEQ; k0 += 64) {
        // ---- load K/V tile (1024 float4 slots over 256 threads) ----
        #pragma unroll
        for (int i = 0; i < 4; i++) {
            const int fi = t + i * 256;
            const int r  = fi >> 4;
            const int c  = (fi & 15) * 4;
            float4 kv = *(const float4*)&kp[(size_t)(k0 + r) * DK + c];
            float4 vv = *(const float4*)&vp[(size_t)(k0 + r) * DK + c];
            uint4 ku = { f2tf32(kv.x), f2tf32(kv.y), f2tf32(kv.z), f2tf32(kv.w) };
            uint4 vu = { f2tf32(vv.x), f2tf32(vv.y), f2tf32(vv.z), f2tf32(vv.w) };
            *(uint4*)&Ksu[r * KPAD + c] = ku;
            *(uint4*)&Vsu[r * VPAD + c] = vu;
        }
        __syncthreads();

        // ---- S = Q K^T ----
        float s[8][4];
        #pragma unroll
        for (int nt = 0; nt < 8; nt++) {
            #pragma unroll
            for (int c = 0; c < 4; c++) s[nt][c] = 0.f;
            const int key = nt * 8 + g;
            #pragma unroll
            for (int ks = 0; ks < 8; ks++) {
                const int d = ks * 8 + tig;
                uint32_t b0 = Ksu[key * KPAD + d];
                uint32_t b1 = Ksu[key * KPAD + d + 4];
                mma_tf32(s[nt], qf[ks][0], qf[ks][1], qf[ks][2], qf[ks][3], b0, b1);
            }
        }

        // ---- online softmax (base-2) ----
        float t0 = -1e30f, t1 = -1e30f;
        #pragma unroll
        for (int nt = 0; nt < 8; nt++) {
            t0 = fmaxf(t0, fmaxf(s[nt][0], s[nt][1]));
            t1 = fmaxf(t1, fmaxf(s[nt][2], s[nt][3]));
        }
        t0 = fmaxf(t0, __shfl_xor_sync(0xffffffffu, t0, 1));
        t0 = fmaxf(t0, __shfl_xor_sync(0xffffffffu, t0, 2));
        t1 = fmaxf(t1, __shfl_xor_sync(0xffffffffu, t1, 1));
        t1 = fmaxf(t1, __shfl_xor_sync(0xffffffffu, t1, 2));
        const float nm0 = fmaxf(m0, t0), nm1 = fmaxf(m1, t1);
        const float cr0 = fexp2(m0 - nm0), cr1 = fexp2(m1 - nm1);

        float p0 = 0.f, p1 = 0.f;
        #pragma unroll
        for (int nt = 0; nt < 8; nt++) {
            s[nt][0] = fexp2(s[nt][0] - nm0);
            s[nt][1] = fexp2(s[nt][1] - nm0);
            s[nt][2] = fexp2(s[nt][2] - nm1);
            s[nt][3] = fexp2(s[nt][3] - nm1);
            p0 += s[nt][0] + s[nt][1];
            p1 += s[nt][2] + s[nt][3];
        }
        p0 += __shfl_xor_sync(0xffffffffu, p0, 1);
        p0 += __shfl_xor_sync(0xffffffffu, p0, 2);
        p1 += __shfl_xor_sync(0xffffffffu, p1, 1);
        p1 += __shfl_xor_sync(0xffffffffu, p1, 2);
        l0 = l0 * cr0 + p0;
        l1 = l1 * cr1 + p1;
        m0 = nm0; m1 = nm1;

        #pragma unroll
        for (int nt = 0; nt < 8; nt++) {
            o[nt][0] *= cr0; o[nt][1] *= cr0;
            o[nt][2] *= cr1; o[nt][3] *= cr1;
        }

        // ---- P -> per-warp smem (tf32) ----
        #pragma unroll
        for (int nt = 0; nt < 8; nt++) {
            const int col = nt * 8 + 2 * tig;
            float2 lo = { __uint_as_float(f2tf32(s[nt][0])),
                          __uint_as_float(f2tf32(s[nt][1])) };
            float2 hi = { __uint_as_float(f2tf32(s[nt][2])),
                          __uint_as_float(f2tf32(s[nt][3])) };
            *(float2*)&Pw[g * PPAD + col]       = lo;
            *(float2*)&Pw[(g + 8) * PPAD + col] = hi;
        }
        __syncwarp();

        // ---- O += P V (A-frags per-ks: reg-lean, 8 indep chains) ----
        #pragma unroll
        for (int ks = 0; ks < 8; ks++) {
            const int kk = ks * 8 + tig;
            const uint32_t a0 = __float_as_uint(Pw[g * PPAD + kk]);
            const uint32_t a1 = __float_as_uint(Pw[(g + 8) * PPAD + kk]);
            const uint32_t a2 = __float_as_uint(Pw[g * PPAD + kk + 4]);
            const uint32_t a3 = __float_as_uint(Pw[(g + 8) * PPAD + kk + 4]);
            const int key = ks * 8 + tig;
            #pragma unroll
            for (int nt = 0; nt < 8; nt++) {
                const int dcol = nt * 8 + g;
                uint32_t b0 = Vsu[key * VPAD + dcol];
                uint32_t b1 = Vsu[(key + 4) * VPAD + dcol];
                mma_tf32(o[nt], a0, a1, a2, a3, b0, b1);
            }
        }
        __syncthreads();
    }

    const float inv0 = 1.0f / l0, inv1 = 1.0f / l1;
    float* oa = g_ao + (size_t)(b * SEQ + row_a) * D_MODEL + h * DK;
    float* ob = oa + (size_t)8 * D_MODEL;
    #pragma unroll
    for (int nt = 0; nt < 8; nt++) {
        const int col = nt * 8 + 2 * tig;
        float2 lo = { o[nt][0] * inv0, o[nt][1] * inv0 };
        float2 hi = { o[nt][2] * inv1, o[nt][3] * inv1 };
        *(float2*)&oa[col] = lo;
        *(float2*)&ob[col] = hi;
    }
}

extern "C" void kernel_launch(void* const* d_in, const int* in_sizes, int n_in,
                              void* d_out, int out_size) {
    const float* q  = (const float*)d_in[0];
    const float* k  = (const float*)d_in[1];
    const float* v  = (const float*)d_in[2];
    const float* Wq = (const float*)d_in[3];
    const float* bq = (const float*)d_in[4];
    const float* Wk = (const float*)d_in[5];
    const float* bk = (const float*)d_in[6];
    const float* Wv = (const float*)d_in[7];
    const float* bv = (const float*)d_in[8];
    const float* Wo = (const float*)d_in[9];
    const float* bo = (const float*)d_in[10];
    float* out = (float*)d_out;

    cudaFuncSetAttribute(gemm_tc,
                         cudaFuncAttributeMaxDynamicSharedMemorySize, GEMM_SMEM);
    cudaFuncSetAttribute(flash_attn_tc,
                         cudaFuncAttributeMaxDynamicSharedMemorySize,
                         ATTN_SMEM_BYTES);

    dim3 gg(MTOT / GM, D_MODEL / GN);     // 32 x 12
    gemm_tc<<<gg, 256, GEMM_SMEM>>>(q, Wq, bq, nullptr, 0);
    gemm_tc<<<gg, 256, GEMM_SMEM>>>(k, Wk, bk, nullptr, 1);
    gemm_tc<<<gg, 256, GEMM_SMEM>>>(v, Wv, bv, nullptr, 2);

    dim3 ga(SEQ / TQ, NHEADS, BATCH);     // 16 x 12 x 2
    flash_attn_tc<<<ga, 256, ATTN_SMEM_BYTES>>>();

    dim3 go(MTOT / GM, D_MODEL / GN);     // 32 x 12
    gemm_tc<<<go, 256, GEMM_SMEM>>>(nullptr, Wo, bo, out, 3);
}

// round 16
// speedup vs baseline: 2.2095x; 1.0255x over previous
#include <cuda_runtime.h>
#include <cstdint>

#define D_MODEL 768
#define NHEADS  12
#define DK      64
#define BATCH   2
#define SEQ     2048
#define MTOT    (BATCH*SEQ)   // 4096

// Scratch (device globals: allocation-free, harness-safe)
__device__ float g_q [BATCH*NHEADS*SEQ*DK];   // [B,H,S,dk]
__device__ float g_k [BATCH*NHEADS*SEQ*DK];
__device__ float g_v [BATCH*NHEADS*SEQ*DK];
__device__ float g_ao[MTOT*D_MODEL];          // [B,S,D] attention output

__device__ __forceinline__ uint32_t f2tf32(float x) {
    uint32_t r;
    asm("cvt.rna.tf32.f32 %0, %1;" : "=r"(r) : "f"(x));
    return r;
}
__device__ __forceinline__ float fexp2(float x) {
    float y;
    asm("ex2.approx.ftz.f32 %0, %1;" : "=f"(y) : "f"(x));
    return y;
}
__device__ __forceinline__ void mma_tf32(float c[4],
        uint32_t a0, uint32_t a1, uint32_t a2, uint32_t a3,
        uint32_t b0, uint32_t b1) {
    asm volatile(
        "mma.sync.aligned.m16n8k8.row.col.f32.tf32.tf32.f32 "
        "{%0,%1,%2,%3}, {%4,%5,%6,%7}, {%8,%9}, {%0,%1,%2,%3};"
        : "+f"(c[0]), "+f"(c[1]), "+f"(c[2]), "+f"(c[3])
        : "r"(a0), "r"(a1), "r"(a2), "r"(a3), "r"(b0), "r"(b1));
}

// ---------------------------------------------------------------------------
// 2-term TF32 tensor-core GEMM with bias — R15 version (proven, ~65us each).
// A rounded once, W split hi/lo: acc += At*Bh + At*Bl.
// Block: 128(M) x 64(N), BK=32. 8 warps in 4(m) x 2(n); warp tile 32x32.
// mode 0/1/2: scatter into g_q/g_k/g_v head-split. mode 3: row-major outp.
// A==nullptr -> read from g_ao.
// ---------------------------------------------------------------------------
#define GM 128
#define GN 64
#define GK 32
#define APAD 36
#define BPAD 72
#define GEMM_SMEM ((128*APAD + 2*GK*BPAD) * 4)   // 36864 B

__global__ __launch_bounds__(256, 2) void gemm_tc(
        const float* __restrict__ A, const float* __restrict__ W,
        const float* __restrict__ bias, float* __restrict__ outp, int mode) {
    extern __shared__ float sm[];
    float* At = sm;                  // [128][APAD]  (single tf32 plane)
    float* Bh = At + 128 * APAD;     // [GK][BPAD]
    float* Bl = Bh + GK * BPAD;

    const float* __restrict__ Ain = A ? A : (const float*)g_ao;
    const int m0 = blockIdx.x * GM, n0 = blockIdx.y * GN;
    const int t = threadIdx.x, warp = t >> 5, lane = t & 31;
    const int g = lane >> 2, tig = lane & 3;
    const int wm = (warp & 3) * 32, wn = (warp >> 2) * 32;

    const int am = t >> 3, ak = (t & 7) * 4;
    const int bk = t >> 4, bn = (t & 15) * 4;

    float4 aS[4], bS[2];
    #pragma unroll
    for (int i = 0; i < 4; i++)
        aS[i] = *(const float4*)&Ain[(size_t)(m0 + am + i*32) * D_MODEL + ak];
    #pragma unroll
    for (int i = 0; i < 2; i++)
        bS[i] = *(const float4*)&W[(size_t)(bk + i*16) * D_MODEL + n0 + bn];

    float acc[2][4][4] = {};

    for (int kt = 0; kt < D_MODEL / GK; kt++) {
        #pragma unroll
        for (int i = 0; i < 4; i++) {
            float4 v = aS[i], h;
            h.x = __uint_as_float(f2tf32(v.x));
            h.y = __uint_as_float(f2tf32(v.y));
            h.z = __uint_as_float(f2tf32(v.z));
            h.w = __uint_as_float(f2tf32(v.w));
            *(float4*)&At[(am + i*32) * APAD + ak] = h;
        }
        #pragma unroll
        for (int i = 0; i < 2; i++) {
            float4 v = bS[i], h, l;
            h.x = __uint_as_float(f2tf32(v.x)); l.x = __uint_as_float(f2tf32(v.x - h.x));
            h.y = __uint_as_float(f2tf32(v.y)); l.y = __uint_as_float(f2tf32(v.y - h.y));
            h.z = __uint_as_float(f2tf32(v.z)); l.z = __uint_as_float(f2tf32(v.z - h.z));
            h.w = __uint_as_float(f2tf32(v.w)); l.w = __uint_as_float(f2tf32(v.w - h.w));
            *(float4*)&Bh[(bk + i*16) * BPAD + bn] = h;
            *(float4*)&Bl[(bk + i*16) * BPAD + bn] = l;
        }
        __syncthreads();

        if (kt + 1 < D_MODEL / GK) {
            const int k0 = (kt + 1) * GK;
            #pragma unroll
            for (int i = 0; i < 4; i++)
                aS[i] = *(const float4*)&Ain[(size_t)(m0 + am + i*32) * D_MODEL + k0 + ak];
            #pragma unroll
            for (int i = 0; i < 2; i++)
                bS[i] = *(const float4*)&W[(size_t)(k0 + bk + i*16) * D_MODEL + n0 + bn];
        }

        #pragma unroll
        for (int kk = 0; kk < 4; kk++) {
            uint32_t af[2][4];
            #pragma unroll
            for (int mi = 0; mi < 2; mi++) {
                const int r0 = (wm + mi*16 + g) * APAD + kk*8 + tig;
                const int r1 = r0 + 8 * APAD;
                af[mi][0] = __float_as_uint(At[r0]);
                af[mi][1] = __float_as_uint(At[r1]);
                af[mi][2] = __float_as_uint(At[r0 + 4]);
                af[mi][3] = __float_as_uint(At[r1 + 4]);
            }
            uint32_t bfh[4][2], bfl[4][2];
            #pragma unroll
            for (int nt = 0; nt < 4; nt++) {
                const int r = (kk*8 + tig) * BPAD + wn + nt*8 + g;
                bfh[nt][0] = __float_as_uint(Bh[r]);
                bfh[nt][1] = __float_as_uint(Bh[r + 4*BPAD]);
                bfl[nt][0] = __float_as_uint(Bl[r]);
                bfl[nt][1] = __float_as_uint(Bl[r + 4*BPAD]);
            }
            #pragma unroll
            for (int mi = 0; mi < 2; mi++)
                #pragma unroll
                for (int nt = 0; nt < 4; nt++) {
                    mma_tf32(acc[mi][nt], af[mi][0], af[mi][1], af[mi][2], af[mi][3],
                             bfh[nt][0], bfh[nt][1]);
                    mma_tf32(acc[mi][nt], af[mi][0], af[mi][1], af[mi][2], af[mi][3],
                             bfl[nt][0], bfl[nt][1]);
                }
        }
        __syncthreads();
    }

    #pragma unroll
    for (int mi = 0; mi < 2; mi++) {
        #pragma unroll
        for (int nt = 0; nt < 4; nt++) {
            const int col = wn + nt*8 + 2*tig;
            const float b0 = bias[n0 + col];
            const float b1 = bias[n0 + col + 1];
            const int mA = m0 + wm + mi*16 + g;
            const int mB = mA + 8;
            float2 vA = { acc[mi][nt][0] + b0, acc[mi][nt][1] + b1 };
            float2 vB = { acc[mi][nt][2] + b0, acc[mi][nt][3] + b1 };
            if (mode == 3) {
                *(float2*)&outp[(size_t)mA * D_MODEL + n0 + col] = vA;
                *(float2*)&outp[(size_t)mB * D_MODEL + n0 + col] = vB;
            } else {
                float* o = (mode == 0) ? g_q : (mode == 1) ? g_k : g_v;
                const int h = n0 >> 6;
                const size_t iA = (((size_t)((mA >> 11) * NHEADS + h) * SEQ)
                                   + (mA & 2047)) * DK + col;
                const size_t iB = (((size_t)((mB >> 11) * NHEADS + h) * SEQ)
                                   + (mB & 2047)) * DK + col;
                *(float2*)&o[iA] = vA;
                *(float2*)&o[iB] = vB;
            }
        }
    }
}

// ---------------------------------------------------------------------------
// Tensor-core (tf32 HMMA) flash attention — KTILE=128: one smem load + one
// barrier pair per 128 keys, processed as two byte-identical 64-key halves.
// Block: 128 queries of one (b,h); 8 warps x 16 rows; 2 CTA/SM (128 regs).
// ---------------------------------------------------------------------------
#define KPAD 68
#define VPAD 72
#define PPAD 68
#define QWARPS 8
#define TQ (QWARPS*16)              // 128 queries per block
#define KTILE 128
#define ATTN_SMEM_BYTES ((KTILE*KPAD + KTILE*VPAD + QWARPS*16*PPAD) * 4)  // 106496

__global__ __launch_bounds__(256, 2) void flash_attn_tc() {
    extern __shared__ uint32_t smem_u[];
    uint32_t* Ksu = smem_u;                             // [128][KPAD]
    uint32_t* Vsu = smem_u + KTILE * KPAD;              // [128][VPAD]
    float*    Psb = (float*)(smem_u + KTILE * KPAD + KTILE * VPAD);

    const int t    = threadIdx.x;
    const int warp = t >> 5;
    const int lane = t & 31;
    const int g    = lane >> 2;
    const int tig  = lane & 3;

    const int qt = blockIdx.x, h = blockIdx.y, b = blockIdx.z;
    const size_t headBase = (size_t)(b * NHEADS + h) * SEQ * DK;
    const float* __restrict__ kp = g_k + headBase;
    const float* __restrict__ vp = g_v + headBase;

    const float qscale = 0.125f * 1.4426950408889634f;
    const int row_a = qt * TQ + warp * 16 + g;
    const float* __restrict__ qa = g_q + headBase + (size_t)row_a * DK;
    const float* __restrict__ qb = qa + 8 * DK;

    uint32_t qf[8][4];
    #pragma unroll
    for (int ks = 0; ks < 8; ks++) {
        const int c0 = 8 * ks + tig;
        qf[ks][0] = f2tf32(qa[c0]     * qscale);
        qf[ks][1] = f2tf32(qb[c0]     * qscale);
        qf[ks][2] = f2tf32(qa[c0 + 4] * qscale);
        qf[ks][3] = f2tf32(qb[c0 + 4] * qscale);
    }

    float o[8][4];
    #pragma unroll
    for (int nt = 0; nt < 8; nt++)
        #pragma unroll
        for (int c = 0; c < 4; c++) o[nt][c] = 0.f;
    float m0 = -1e30f, m1 = -1e30f, l0 = 0.f, l1 = 0.f;

    float* Pw = Psb + warp * 16 * PPAD;

    for (int k0 = 0; k0 < SEQ; k0 += KTILE) {
        // ---- load 128x64 K and V (2048 float4 slots over 256 threads) ----
        #pragma unroll
        for (int i = 0; i < 8; i++) {
            const int fi = t + i * 256;
            const int r  = fi >> 4;             // 0..127
            const int c  = (fi & 15) * 4;
            float4 kv = *(const float4*)&kp[(size_t)(k0 + r) * DK + c];
            float4 vv = *(const float4*)&vp[(size_t)(k0 + r) * DK + c];
            uint4 ku = { f2tf32(kv.x), f2tf32(kv.y), f2tf32(kv.z), f2tf32(kv.w) };
            uint4 vu = { f2tf32(vv.x), f2tf32(vv.y), f2tf32(vv.z), f2tf32(vv.w) };
            *(uint4*)&Ksu[r * KPAD + c] = ku;
            *(uint4*)&Vsu[r * VPAD + c] = vu;
        }
        __syncthreads();

        // ---- two 64-key halves; no barrier between (warp-private P) ----
        #pragma unroll
        for (int half = 0; half < 2; half++) {
            const uint32_t* Kh_ = Ksu + half * 64 * KPAD;
            const uint32_t* Vh_ = Vsu + half * 64 * VPAD;

            // S = Q K^T
            float s[8][4];
            #pragma unroll
            for (int nt = 0; nt < 8; nt++) {
                #pragma unroll
                for (int c = 0; c < 4; c++) s[nt][c] = 0.f;
                const int key = nt * 8 + g;
                #pragma unroll
                for (int ks = 0; ks < 8; ks++) {
                    const int d = ks * 8 + tig;
                    uint32_t b0 = Kh_[key * KPAD + d];
                    uint32_t b1 = Kh_[key * KPAD + d + 4];
                    mma_tf32(s[nt], qf[ks][0], qf[ks][1], qf[ks][2], qf[ks][3], b0, b1);
                }
            }

            // online softmax (base-2)
            float t0 = -1e30f, t1 = -1e30f;
            #pragma unroll
            for (int nt = 0; nt < 8; nt++) {
                t0 = fmaxf(t0, fmaxf(s[nt][0], s[nt][1]));
                t1 = fmaxf(t1, fmaxf(s[nt][2], s[nt][3]));
            }
            t0 = fmaxf(t0, __shfl_xor_sync(0xffffffffu, t0, 1));
            t0 = fmaxf(t0, __shfl_xor_sync(0xffffffffu, t0, 2));
            t1 = fmaxf(t1, __shfl_xor_sync(0xffffffffu, t1, 1));
            t1 = fmaxf(t1, __shfl_xor_sync(0xffffffffu, t1, 2));
            const float nm0 = fmaxf(m0, t0), nm1 = fmaxf(m1, t1);
            const float cr0 = fexp2(m0 - nm0), cr1 = fexp2(m1 - nm1);

            float p0 = 0.f, p1 = 0.f;
            #pragma unroll
            for (int nt = 0; nt < 8; nt++) {
                s[nt][0] = fexp2(s[nt][0] - nm0);
                s[nt][1] = fexp2(s[nt][1] - nm0);
                s[nt][2] = fexp2(s[nt][2] - nm1);
                s[nt][3] = fexp2(s[nt][3] - nm1);
                p0 += s[nt][0] + s[nt][1];
                p1 += s[nt][2] + s[nt][3];
            }
            p0 += __shfl_xor_sync(0xffffffffu, p0, 1);
            p0 += __shfl_xor_sync(0xffffffffu, p0, 2);
            p1 += __shfl_xor_sync(0xffffffffu, p1, 1);
            p1 += __shfl_xor_sync(0xffffffffu, p1, 2);
            l0 = l0 * cr0 + p0;
            l1 = l1 * cr1 + p1;
            m0 = nm0; m1 = nm1;

            #pragma unroll
            for (int nt = 0; nt < 8; nt++) {
                o[nt][0] *= cr0; o[nt][1] *= cr0;
                o[nt][2] *= cr1; o[nt][3] *= cr1;
            }

            // P -> per-warp smem (tf32)
            #pragma unroll
            for (int nt = 0; nt < 8; nt++) {
                const int col = nt * 8 + 2 * tig;
                float2 lo = { __uint_as_float(f2tf32(s[nt][0])),
                              __uint_as_float(f2tf32(s[nt][1])) };
                float2 hi = { __uint_as_float(f2tf32(s[nt][2])),
                              __uint_as_float(f2tf32(s[nt][3])) };
                *(float2*)&Pw[g * PPAD + col]       = lo;
                *(float2*)&Pw[(g + 8) * PPAD + col] = hi;
            }
            __syncwarp();

            // O += P V (A-frags per-ks: reg-lean, 8 indep chains)
            #pragma unroll
            for (int ks = 0; ks < 8; ks++) {
                const int kk = ks * 8 + tig;
                const uint32_t a0 = __float_as_uint(Pw[g * PPAD + kk]);
                const uint32_t a1 = __float_as_uint(Pw[(g + 8) * PPAD + kk]);
                const uint32_t a2 = __float_as_uint(Pw[g * PPAD + kk + 4]);
                const uint32_t a3 = __float_as_uint(Pw[(g + 8) * PPAD + kk + 4]);
                const int key = ks * 8 + tig;
                #pragma unroll
                for (int nt = 0; nt < 8; nt++) {
                    const int dcol = nt * 8 + g;
                    uint32_t b0 = Vh_[key * VPAD + dcol];
                    uint32_t b1 = Vh_[(key + 4) * VPAD + dcol];
                    mma_tf32(o[nt], a0, a1, a2, a3, b0, b1);
                }
            }
            __syncwarp();   // P reads done before next half overwrites Pw
        }
        __syncthreads();    // K/V consumed before next tile's stores
    }

    const float inv0 = 1.0f / l0, inv1 = 1.0f / l1;
    float* oa = g_ao + (size_t)(b * SEQ + row_a) * D_MODEL + h * DK;
    float* ob = oa + (size_t)8 * D_MODEL;
    #pragma unroll
    for (int nt = 0; nt < 8; nt++) {
        const int col = nt * 8 + 2 * tig;
        float2 lo = { o[nt][0] * inv0, o[nt][1] * inv0 };
        float2 hi = { o[nt][2] * inv1, o[nt][3] * inv1 };
        *(float2*)&oa[col] = lo;
        *(float2*)&ob[col] = hi;
    }
}

extern "C" void kernel_launch(void* const* d_in, const int* in_sizes, int n_in,
                              void* d_out, int out_size) {
    const float* q  = (const float*)d_in[0];
    const float* k  = (const float*)d_in[1];
    const float* v  = (const float*)d_in[2];
    const float* Wq = (const float*)d_in[3];
    const float* bq = (const float*)d_in[4];
    const float* Wk = (const float*)d_in[5];
    const float* bk = (const float*)d_in[6];
    const float* Wv = (const float*)d_in[7];
    const float* bv = (const float*)d_in[8];
    const float* Wo = (const float*)d_in[9];
    const float* bo = (const float*)d_in[10];
    float* out = (float*)d_out;

    cudaFuncSetAttribute(gemm_tc,
                         cudaFuncAttributeMaxDynamicSharedMemorySize, GEMM_SMEM);
    cudaFuncSetAttribute(flash_attn_tc,
                         cudaFuncAttributeMaxDynamicSharedMemorySize,
                         ATTN_SMEM_BYTES);

    dim3 gg(MTOT / GM, D_MODEL / GN);     // 32 x 12
    gemm_tc<<<gg, 256, GEMM_SMEM>>>(q, Wq, bq, nullptr, 0);
    gemm_tc<<<gg, 256, GEMM_SMEM>>>(k, Wk, bk, nullptr, 1);
    gemm_tc<<<gg, 256, GEMM_SMEM>>>(v, Wv, bv, nullptr, 2);

    dim3 ga(SEQ / TQ, NHEADS, BATCH);     // 16 x 12 x 2
    flash_attn_tc<<<ga, 256, ATTN_SMEM_BYTES>>>();

    dim3 go(MTOT / GM, D_MODEL / GN);     // 32 x 12
    gemm_tc<<<go, 256, GEMM_SMEM>>>(nullptr, Wo, bo, out, 3);
}